// round 14
// baseline (speedup 1.0000x reference)
#include <cuda_runtime.h>
#include <cuda_fp16.h>
#include <math.h>
#include <stdint.h>

#define NNODES 50000
#define NEDGES 800000
#define NTOK   100000
#define SEQLEN 32
#define EMBD   128
#define INFEAT 256
#define NHID   256
#define NCLS   40

#define CHUNK   512
#define NCHUNK  98      // 98*512 = 50176 >= 50000
#define MTILES  391     // ceil(50000/128)

typedef unsigned long long ull;

// ---------------- scratch (device globals; no allocation allowed) ------------
__device__ int   g_deg_out[NNODES];
__device__ int   g_deg_in[NNODES];
__device__ float g_norm_s[NNODES];
__device__ float g_norm_d[NNODES];
__device__ int   g_row_ptr[NNODES + 1];
__device__ int   g_cursor[NNODES];
__device__ int   g_chunk_sum[NCHUNK];
__device__ int   g_chunk_off[NCHUNK];
__device__ int   g_csr_src[NEDGES];
__device__ __align__(16) __half g_hh[(size_t)NNODES * INFEAT];    // pooled emb fp16
__device__ __align__(16) __half g_w1h[NHID * INFEAT];             // W1^T [n][k] fp16
__device__ __align__(16) __half g_hw1h[(size_t)NNODES * NHID];    // h@W1 fp16
__device__ __align__(16) __half g_out1h[(size_t)NNODES * NHID];   // relu(...) fp16
__device__ __align__(16) __half g_hws2h[(size_t)NNODES * NCLS];   // (out1@W2)*norm_s fp16

// ---------------- helpers -----------------------------------------------------
__device__ __forceinline__ ull ffma2(ull a, ull b, ull c) {
    ull d;
    asm("fma.rn.f32x2 %0, %1, %2, %3;" : "=l"(d) : "l"(a), "l"(b), "l"(c));
    return d;
}
__device__ __forceinline__ ull dup2(float x) {
    ull d;
    asm("mov.b64 %0, {%1, %1};" : "=l"(d) : "f"(x));
    return d;
}
__device__ __forceinline__ void unpack2(ull v, float& lo, float& hi) {
    asm("mov.b64 {%0, %1}, %2;" : "=f"(lo), "=f"(hi) : "l"(v));
}
__device__ __forceinline__ void mma_f16(float* c, const uint32_t* a, uint32_t b0, uint32_t b1) {
    asm volatile(
        "mma.sync.aligned.m16n8k16.row.col.f32.f16.f16.f32 "
        "{%0,%1,%2,%3}, {%4,%5,%6,%7}, {%8,%9}, {%0,%1,%2,%3};"
        : "+f"(c[0]), "+f"(c[1]), "+f"(c[2]), "+f"(c[3])
        : "r"(a[0]), "r"(a[1]), "r"(a[2]), "r"(a[3]), "r"(b0), "r"(b1));
}

// ---------------- degree ------------------------------------------------------
__global__ void zero_degs_kernel() {
    int i = blockIdx.x * blockDim.x + threadIdx.x;
    if (i < NNODES) { g_deg_out[i] = 0; g_deg_in[i] = 0; }
}

__global__ void degree_kernel(const int* __restrict__ src, const int* __restrict__ dst) {
    int e = blockIdx.x * blockDim.x + threadIdx.x;
    if (e < NEDGES) {
        atomicAdd(&g_deg_out[src[e]], 1);
        atomicAdd(&g_deg_in[dst[e]], 1);
    }
}

// ---------------- scan + norms ------------------------------------------------
__global__ void scanA_kernel() {
    __shared__ int s[CHUNK];
    int t = threadIdx.x, b = blockIdx.x;
    int idx = b * CHUNK + t;
    int v = (idx < NNODES) ? g_deg_in[idx] : 0;
    s[t] = v;
    __syncthreads();
    for (int off = CHUNK / 2; off > 0; off >>= 1) {
        if (t < off) s[t] += s[t + off];
        __syncthreads();
    }
    if (t == 0) g_chunk_sum[b] = s[0];
}

__global__ void scanB_kernel() {
    __shared__ int s[128];
    int t = threadIdx.x;
    int v = (t < NCHUNK) ? g_chunk_sum[t] : 0;
    s[t] = v;
    __syncthreads();
    for (int off = 1; off < 128; off <<= 1) {
        int x = (t >= off) ? s[t - off] : 0;
        __syncthreads();
        s[t] += x;
        __syncthreads();
    }
    if (t < NCHUNK) g_chunk_off[t] = s[t] - v;
    if (t == 0) g_row_ptr[NNODES] = NEDGES;
}

__global__ void scanC_kernel() {
    __shared__ int s[CHUNK];
    int t = threadIdx.x, b = blockIdx.x;
    int idx = b * CHUNK + t;
    int v = (idx < NNODES) ? g_deg_in[idx] : 0;
    s[t] = v;
    __syncthreads();
    for (int off = 1; off < CHUNK; off <<= 1) {
        int x = (t >= off) ? s[t - off] : 0;
        __syncthreads();
        s[t] += x;
        __syncthreads();
    }
    if (idx < NNODES) {
        int excl = g_chunk_off[b] + s[t] - v;
        g_row_ptr[idx] = excl;
        g_cursor[idx]  = excl;
        int dins = v; if (dins < 1) dins = 1;
        int dofs = g_deg_out[idx]; if (dofs < 1) dofs = 1;
        g_norm_d[idx] = rsqrtf((float)dins);
        g_norm_s[idx] = rsqrtf((float)dofs);
    }
}

__global__ void csr_fill_kernel(const int* __restrict__ src, const int* __restrict__ dst) {
    int e = blockIdx.x * blockDim.x + threadIdx.x;
    if (e < NEDGES) {
        int d = dst[e];
        int pos = atomicAdd(&g_cursor[d], 1);
        g_csr_src[pos] = src[e];
    }
}

// ---------------- embedding pooling (warp per node, fp16 output) -------------
// 2-way interleaved accumulators -> doubled MLP on the L2 gather.
__global__ void embed_kernel(const int* __restrict__ feats, const float* __restrict__ emb) {
    int gt   = blockIdx.x * blockDim.x + threadIdx.x;
    int node = gt >> 5;
    int lane = gt & 31;
    if (node >= NNODES) return;

    int tok = feats[node * SEQLEN + lane];
    int cnt = __popc(__ballot_sync(0xffffffffu, tok != 0));
    if (cnt < 1) cnt = 1;

    float4 s0  = make_float4(0.f, 0.f, 0.f, 0.f);
    float4 s1  = make_float4(0.f, 0.f, 0.f, 0.f);
    float4 mx0 = make_float4(-INFINITY, -INFINITY, -INFINITY, -INFINITY);
    float4 mx1 = make_float4(-INFINITY, -INFINITY, -INFINITY, -INFINITY);

#pragma unroll
    for (int t = 0; t < 32; t += 2) {
        int tk0 = __shfl_sync(0xffffffffu, tok, t);
        int tk1 = __shfl_sync(0xffffffffu, tok, t + 1);
        float4 v0 = make_float4(0.f, 0.f, 0.f, 0.f);
        float4 v1 = make_float4(0.f, 0.f, 0.f, 0.f);
        if (tk0 != 0) v0 = *(const float4*)&emb[(size_t)tk0 * EMBD + lane * 4];
        if (tk1 != 0) v1 = *(const float4*)&emb[(size_t)tk1 * EMBD + lane * 4];
        s0.x += v0.x; s0.y += v0.y; s0.z += v0.z; s0.w += v0.w;
        s1.x += v1.x; s1.y += v1.y; s1.z += v1.z; s1.w += v1.w;
        mx0.x = fmaxf(mx0.x, v0.x); mx0.y = fmaxf(mx0.y, v0.y);
        mx0.z = fmaxf(mx0.z, v0.z); mx0.w = fmaxf(mx0.w, v0.w);
        mx1.x = fmaxf(mx1.x, v1.x); mx1.y = fmaxf(mx1.y, v1.y);
        mx1.z = fmaxf(mx1.z, v1.z); mx1.w = fmaxf(mx1.w, v1.w);
    }
    float4 s = make_float4(s0.x + s1.x, s0.y + s1.y, s0.z + s1.z, s0.w + s1.w);
    float4 mx = make_float4(fmaxf(mx0.x, mx1.x), fmaxf(mx0.y, mx1.y),
                            fmaxf(mx0.z, mx1.z), fmaxf(mx0.w, mx1.w));
    float inv = 1.0f / (float)cnt;
    __half2 h0 = __float22half2_rn(make_float2(s.x * inv, s.y * inv));
    __half2 h1 = __float22half2_rn(make_float2(s.z * inv, s.w * inv));
    __half2 m0 = __float22half2_rn(make_float2(mx.x, mx.y));
    __half2 m1 = __float22half2_rn(make_float2(mx.z, mx.w));
    size_t base = (size_t)node * INFEAT;
    *(uint2*)&g_hh[base + lane * 4]        = make_uint2(*(unsigned*)&h0, *(unsigned*)&h1);
    *(uint2*)&g_hh[base + EMBD + lane * 4] = make_uint2(*(unsigned*)&m0, *(unsigned*)&m1);
}

// ---------------- prep W1: [K][N] fp32 -> [N][K] fp16 ------------------------
__global__ void prep_w1_kernel(const float* __restrict__ W1) {
    int i = blockIdx.x * blockDim.x + threadIdx.x;   // 65536
    int n = i >> 8, k = i & 255;
    g_w1h[n * INFEAT + k] = __float2half(W1[k * NHID + n]);
}

// ---------------- GEMM1 via mma.sync fp16 m16n8k16 (round-13, unchanged) -----
#define KC 32
#define AW 20                   // words per smem row (32 halves + 8 pad)
#define STAGE_W (128 * AW)
#define G1_SMEM (4 * STAGE_W * 4)   // 40960 bytes

__global__ __launch_bounds__(256, 2)
void gemm1_mma_kernel() {
    extern __shared__ __align__(16) uint32_t smem[];
    uint32_t* As = smem;
    uint32_t* Bs = smem + 2 * STAGE_W;

    int tid = threadIdx.x, wid = tid >> 5, lane = tid & 31;
    int wm = wid & 3, wn = wid >> 2;
    int g = lane >> 2, tig = lane & 3;
    int bm = blockIdx.x * 128, bn = blockIdx.y * 128;

    int lrow = tid >> 1, lhw = (tid & 1) * 8;

    float acc[2][8][4];
#pragma unroll
    for (int mi = 0; mi < 2; mi++)
#pragma unroll
        for (int ni = 0; ni < 8; ni++)
#pragma unroll
            for (int q = 0; q < 4; q++) acc[mi][ni][q] = 0.f;

    uint4 ar[2], br[2];
    {
        int arow = bm + lrow;
        ar[0] = make_uint4(0, 0, 0, 0); ar[1] = ar[0];
        if (arow < NNODES) {
            const uint4* sa = (const uint4*)&g_hh[(size_t)arow * INFEAT + 2 * lhw];
            ar[0] = sa[0]; ar[1] = sa[1];
        }
        const uint4* sb = (const uint4*)&g_w1h[(bn + lrow) * INFEAT + 2 * lhw];
        br[0] = sb[0]; br[1] = sb[1];
    }
    *(uint4*)&As[lrow * AW + lhw]     = ar[0];
    *(uint4*)&As[lrow * AW + lhw + 4] = ar[1];
    *(uint4*)&Bs[lrow * AW + lhw]     = br[0];
    *(uint4*)&Bs[lrow * AW + lhw + 4] = br[1];
    __syncthreads();

    const int NKC = INFEAT / KC;   // 8
    for (int kc = 0; kc < NKC; kc++) {
        int cur = kc & 1, nxt = cur ^ 1;
        if (kc + 1 < NKC) {
            int k0 = (kc + 1) * KC;
            int arow = bm + lrow;
            ar[0] = make_uint4(0, 0, 0, 0); ar[1] = ar[0];
            if (arow < NNODES) {
                const uint4* sa = (const uint4*)&g_hh[(size_t)arow * INFEAT + k0 + 2 * lhw];
                ar[0] = sa[0]; ar[1] = sa[1];
            }
            const uint4* sb = (const uint4*)&g_w1h[(bn + lrow) * INFEAT + k0 + 2 * lhw];
            br[0] = sb[0]; br[1] = sb[1];
        }

        const uint32_t* Ac = &As[cur * STAGE_W];
        const uint32_t* Bc = &Bs[cur * STAGE_W];
#pragma unroll
        for (int ks = 0; ks < 2; ks++) {
            int kb = ks * 8 + tig;
            uint32_t af[2][4];
#pragma unroll
            for (int mi = 0; mi < 2; mi++) {
                int r = wm * 32 + mi * 16 + g;
                af[mi][0] = Ac[r * AW + kb];
                af[mi][1] = Ac[(r + 8) * AW + kb];
                af[mi][2] = Ac[r * AW + kb + 4];
                af[mi][3] = Ac[(r + 8) * AW + kb + 4];
            }
#pragma unroll
            for (int ni = 0; ni < 8; ni++) {
                int nr = wn * 64 + ni * 8 + g;
                uint32_t b0 = Bc[nr * AW + kb];
                uint32_t b1 = Bc[nr * AW + kb + 4];
                mma_f16(acc[0][ni], af[0], b0, b1);
                mma_f16(acc[1][ni], af[1], b0, b1);
            }
        }

        if (kc + 1 < NKC) {
            __syncthreads();
            *(uint4*)&As[nxt * STAGE_W + lrow * AW + lhw]     = ar[0];
            *(uint4*)&As[nxt * STAGE_W + lrow * AW + lhw + 4] = ar[1];
            *(uint4*)&Bs[nxt * STAGE_W + lrow * AW + lhw]     = br[0];
            *(uint4*)&Bs[nxt * STAGE_W + lrow * AW + lhw + 4] = br[1];
            __syncthreads();
        }
    }

#pragma unroll
    for (int mi = 0; mi < 2; mi++) {
        int r0 = bm + wm * 32 + mi * 16 + g;
        int r1 = r0 + 8;
#pragma unroll
        for (int ni = 0; ni < 8; ni++) {
            int col = bn + wn * 64 + ni * 8 + tig * 2;
            if (r0 < NNODES) {
                __half2 p = __float22half2_rn(make_float2(acc[mi][ni][0], acc[mi][ni][1]));
                *(unsigned*)&g_hw1h[(size_t)r0 * NHID + col] = *(unsigned*)&p;
            }
            if (r1 < NNODES) {
                __half2 p = __float22half2_rn(make_float2(acc[mi][ni][2], acc[mi][ni][3]));
                *(unsigned*)&g_hw1h[(size_t)r1 * NHID + col] = *(unsigned*)&p;
            }
        }
    }
}

// ---------------- agg layer 1 (fp16 messages, unroll x4) ---------------------
__global__ void agg1_kernel(const float* __restrict__ b1) {
    int gt   = blockIdx.x * blockDim.x + threadIdx.x;
    int node = gt >> 5;
    int lane = gt & 31;
    if (node >= NNODES) return;

    int beg = g_row_ptr[node], end = g_row_ptr[node + 1];
    float acc[8] = {0.f, 0.f, 0.f, 0.f, 0.f, 0.f, 0.f, 0.f};

    int e = beg;
    for (; e + 3 < end; e += 4) {
        int s0 = g_csr_src[e],     s1 = g_csr_src[e + 1];
        int s2 = g_csr_src[e + 2], s3 = g_csr_src[e + 3];
        float n0 = g_norm_s[s0], n1 = g_norm_s[s1];
        float n2 = g_norm_s[s2], n3 = g_norm_s[s3];
        uint4 u0 = *(const uint4*)&g_hw1h[(size_t)s0 * NHID + lane * 8];
        uint4 u1 = *(const uint4*)&g_hw1h[(size_t)s1 * NHID + lane * 8];
        uint4 u2 = *(const uint4*)&g_hw1h[(size_t)s2 * NHID + lane * 8];
        uint4 u3 = *(const uint4*)&g_hw1h[(size_t)s3 * NHID + lane * 8];
        const unsigned* w0 = &u0.x; const unsigned* w1 = &u1.x;
        const unsigned* w2 = &u2.x; const unsigned* w3 = &u3.x;
#pragma unroll
        for (int j = 0; j < 4; j++) {
            float2 f0 = __half22float2(*(const __half2*)&w0[j]);
            float2 f1 = __half22float2(*(const __half2*)&w1[j]);
            float2 f2 = __half22float2(*(const __half2*)&w2[j]);
            float2 f3 = __half22float2(*(const __half2*)&w3[j]);
            acc[2 * j]     += (f0.x * n0 + f1.x * n1) + (f2.x * n2 + f3.x * n3);
            acc[2 * j + 1] += (f0.y * n0 + f1.y * n1) + (f2.y * n2 + f3.y * n3);
        }
    }
    for (; e < end; e++) {
        int s0 = g_csr_src[e];
        float n0 = g_norm_s[s0];
        uint4 u0 = *(const uint4*)&g_hw1h[(size_t)s0 * NHID + lane * 8];
        const unsigned* w0 = &u0.x;
#pragma unroll
        for (int j = 0; j < 4; j++) {
            float2 f0 = __half22float2(*(const __half2*)&w0[j]);
            acc[2 * j]     += f0.x * n0;
            acc[2 * j + 1] += f0.y * n0;
        }
    }

    float nd = g_norm_d[node];
    float4 bb0 = *(const float4*)&b1[lane * 8];
    float4 bb1 = *(const float4*)&b1[lane * 8 + 4];
    float o[8];
    o[0] = fmaxf(acc[0] * nd + bb0.x, 0.f);
    o[1] = fmaxf(acc[1] * nd + bb0.y, 0.f);
    o[2] = fmaxf(acc[2] * nd + bb0.z, 0.f);
    o[3] = fmaxf(acc[3] * nd + bb0.w, 0.f);
    o[4] = fmaxf(acc[4] * nd + bb1.x, 0.f);
    o[5] = fmaxf(acc[5] * nd + bb1.y, 0.f);
    o[6] = fmaxf(acc[6] * nd + bb1.z, 0.f);
    o[7] = fmaxf(acc[7] * nd + bb1.w, 0.f);
    __half2 p0 = __float22half2_rn(make_float2(o[0], o[1]));
    __half2 p1 = __float22half2_rn(make_float2(o[2], o[3]));
    __half2 p2 = __float22half2_rn(make_float2(o[4], o[5]));
    __half2 p3 = __float22half2_rn(make_float2(o[6], o[7]));
    *(uint4*)&g_out1h[(size_t)node * NHID + lane * 8] =
        make_uint4(*(unsigned*)&p0, *(unsigned*)&p1, *(unsigned*)&p2, *(unsigned*)&p3);
}

// ---------------- GEMM2: hws2h = fp16((out1 @ W2) * norm_s), f32x2 -----------
__global__ __launch_bounds__(256)
void gemm2_kernel(const float* __restrict__ W2) {
    __shared__ __align__(16) float Ws[NHID * NCLS];
    for (int i = threadIdx.x; i < (NHID * NCLS) / 4; i += blockDim.x)
        ((float4*)Ws)[i] = ((const float4*)W2)[i];
    __syncthreads();

    int row = blockIdx.x * blockDim.x + threadIdx.x;
    if (row >= NNODES) return;

    ull acc[NCLS / 2];
#pragma unroll
    for (int c = 0; c < NCLS / 2; c++) acc[c] = 0ull;

    const __half* a = &g_out1h[(size_t)row * NHID];
    for (int k0 = 0; k0 < NHID; k0 += 8) {
        uint4 u = *(const uint4*)&a[k0];
        const unsigned* uw = &u.x;
        float a8[8];
#pragma unroll
        for (int j = 0; j < 4; j++) {
            float2 f = __half22float2(*(const __half2*)&uw[j]);
            a8[2 * j] = f.x; a8[2 * j + 1] = f.y;
        }
#pragma unroll
        for (int kk = 0; kk < 8; kk++) {
            ull ad = dup2(a8[kk]);
            const ull* w = (const ull*)&Ws[(k0 + kk) * NCLS];
#pragma unroll
            for (int c = 0; c < NCLS / 2; c++) acc[c] = ffma2(ad, w[c], acc[c]);
        }
    }
    float ns = g_norm_s[row];
    unsigned po[NCLS / 2];
#pragma unroll
    for (int c = 0; c < NCLS / 2; c++) {
        float lo, hi;
        unpack2(acc[c], lo, hi);
        __half2 p = __float22half2_rn(make_float2(lo * ns, hi * ns));
        po[c] = *(unsigned*)&p;
    }
    uint4* dst = (uint4*)&g_hws2h[(size_t)row * NCLS];
#pragma unroll
    for (int c = 0; c < NCLS / 8; c++)
        dst[c] = make_uint4(po[4 * c], po[4 * c + 1], po[4 * c + 2], po[4 * c + 3]);
}

// ---------------- agg layer 2 (fp16 messages) --------------------------------
__global__ void agg2_kernel(const float* __restrict__ b2, float* __restrict__ out) {
    int gt   = blockIdx.x * blockDim.x + threadIdx.x;
    int node = gt >> 5;
    int lane = gt & 31;
    if (node >= NNODES) return;

    int beg = g_row_ptr[node], end = g_row_ptr[node + 1];
    float2 acc = make_float2(0.f, 0.f);
    bool act = lane < (NCLS / 2);
    for (int e = beg; e < end; e++) {
        int s = g_csr_src[e];
        unsigned w = act ? *(const unsigned*)&g_hws2h[(size_t)s * NCLS + lane * 2] : 0u;
        float2 f = __half22float2(*(const __half2*)&w);
        acc.x += f.x; acc.y += f.y;
    }
    if (act) {
        float nd = g_norm_d[node];
        float2 bb = *(const float2*)&b2[lane * 2];
        *(float2*)&out[(size_t)node * NCLS + lane * 2] =
            make_float2(acc.x * nd + bb.x, acc.y * nd + bb.y);
    }
}

// ---------------- launch ------------------------------------------------------
static cudaStream_t g_s2 = 0;
static cudaEvent_t  g_ev_fork = 0, g_ev_w1 = 0, g_ev_join = 0;

extern "C" void kernel_launch(void* const* d_in, const int* in_sizes, int n_in,
                              void* d_out, int out_size) {
    const int*   feats = (const int*)d_in[0];
    const int*   src   = (const int*)d_in[1];
    const int*   dst   = (const int*)d_in[2];
    const float* emb   = (const float*)d_in[3];
    const float* W1    = (const float*)d_in[4];
    const float* b1    = (const float*)d_in[5];
    const float* W2    = (const float*)d_in[6];
    const float* b2    = (const float*)d_in[7];
    float*       out   = (float*)d_out;

    if (!g_s2) {
        cudaStreamCreateWithFlags(&g_s2, cudaStreamNonBlocking);
        cudaEventCreateWithFlags(&g_ev_fork, cudaEventDisableTiming);
        cudaEventCreateWithFlags(&g_ev_w1, cudaEventDisableTiming);
        cudaEventCreateWithFlags(&g_ev_join, cudaEventDisableTiming);
        cudaFuncSetAttribute(gemm1_mma_kernel,
                             cudaFuncAttributeMaxDynamicSharedMemorySize, G1_SMEM);
    }

    // fork side stream
    cudaEventRecord(g_ev_fork, 0);
    cudaStreamWaitEvent(g_s2, g_ev_fork, 0);

    // CSR chain on s2; main chain ordered so agg1 is launch idx 3 (ncu slot)
    embed_kernel<<<(NNODES * 32 + 255) / 256, 256>>>(feats, emb);          // 0 main
    prep_w1_kernel<<<256, 256, 0, g_s2>>>(W1);                             // 1 s2
    cudaEventRecord(g_ev_w1, g_s2);
    cudaStreamWaitEvent(0, g_ev_w1, 0);
    gemm1_mma_kernel<<<dim3(MTILES, 2), 256, G1_SMEM>>>();                 // 2 main
    zero_degs_kernel<<<(NNODES + 511) / 512, 512, 0, g_s2>>>();            // (s2)
    degree_kernel<<<(NEDGES + 511) / 512, 512, 0, g_s2>>>(src, dst);       // (s2)
    scanA_kernel<<<NCHUNK, CHUNK, 0, g_s2>>>();                            // (s2)
    scanB_kernel<<<1, 128, 0, g_s2>>>();                                   // (s2)
    scanC_kernel<<<NCHUNK, CHUNK, 0, g_s2>>>();                            // (s2)
    csr_fill_kernel<<<(NEDGES + 511) / 512, 512, 0, g_s2>>>(src, dst);     // (s2)
    cudaEventRecord(g_ev_join, g_s2);

    // agg1 needs CSR + norms (s2) and gemm1 (main) — launch idx 3 on main
    cudaStreamWaitEvent(0, g_ev_join, 0);
    agg1_kernel<<<(NNODES * 32 + 255) / 256, 256>>>(b1);                   // 3 main
    gemm2_kernel<<<(NNODES + 255) / 256, 256>>>(W2);
    agg2_kernel<<<(NNODES * 32 + 255) / 256, 256>>>(b2, out);
}

// round 15
// speedup vs baseline: 1.0038x; 1.0038x over previous
#include <cuda_runtime.h>
#include <cuda_fp16.h>
#include <math.h>
#include <stdint.h>

#define NNODES 50000
#define NEDGES 800000
#define NTOK   100000
#define SEQLEN 32
#define EMBD   128
#define INFEAT 256
#define NHID   256
#define NCLS   40

#define CHUNK   512
#define NCHUNK  98      // 98*512 = 50176 >= 50000
#define MTILES  391     // ceil(50000/128)

typedef unsigned long long ull;

// ---------------- scratch (device globals; no allocation allowed) ------------
__device__ int   g_deg_out[NNODES];
__device__ int   g_deg_in[NNODES];
__device__ float g_norm_s[NNODES];
__device__ float g_norm_d[NNODES];
__device__ int   g_row_ptr[NNODES + 1];
__device__ int   g_cursor[NNODES];
__device__ int   g_chunk_sum[NCHUNK];
__device__ int   g_chunk_off[NCHUNK];
__device__ int   g_csr_src[NEDGES];
__device__ __align__(16) __half g_hh[(size_t)NNODES * INFEAT];    // pooled emb fp16
__device__ __align__(16) __half g_w1h[NHID * INFEAT];             // W1^T [n][k] fp16
__device__ __align__(16) __half g_hw1h[(size_t)NNODES * NHID];    // h@W1 fp16
__device__ __align__(16) __half g_out1h[(size_t)NNODES * NHID];   // relu(...) fp16
__device__ __align__(16) __half g_hws2h[(size_t)NNODES * NCLS];   // (out1@W2)*norm_s fp16

// ---------------- helpers -----------------------------------------------------
__device__ __forceinline__ ull ffma2(ull a, ull b, ull c) {
    ull d;
    asm("fma.rn.f32x2 %0, %1, %2, %3;" : "=l"(d) : "l"(a), "l"(b), "l"(c));
    return d;
}
__device__ __forceinline__ ull dup2(float x) {
    ull d;
    asm("mov.b64 %0, {%1, %1};" : "=l"(d) : "f"(x));
    return d;
}
__device__ __forceinline__ void unpack2(ull v, float& lo, float& hi) {
    asm("mov.b64 {%0, %1}, %2;" : "=f"(lo), "=f"(hi) : "l"(v));
}
__device__ __forceinline__ void mma_f16(float* c, const uint32_t* a, uint32_t b0, uint32_t b1) {
    asm volatile(
        "mma.sync.aligned.m16n8k16.row.col.f32.f16.f16.f32 "
        "{%0,%1,%2,%3}, {%4,%5,%6,%7}, {%8,%9}, {%0,%1,%2,%3};"
        : "+f"(c[0]), "+f"(c[1]), "+f"(c[2]), "+f"(c[3])
        : "r"(a[0]), "r"(a[1]), "r"(a[2]), "r"(a[3]), "r"(b0), "r"(b1));
}

// ---------------- degree ------------------------------------------------------
__global__ void zero_degs_kernel() {
    int i = blockIdx.x * blockDim.x + threadIdx.x;
    if (i < NNODES) { g_deg_out[i] = 0; g_deg_in[i] = 0; }
}

__global__ void degree_kernel(const int* __restrict__ src, const int* __restrict__ dst) {
    int e = blockIdx.x * blockDim.x + threadIdx.x;
    if (e < NEDGES) {
        atomicAdd(&g_deg_out[src[e]], 1);
        atomicAdd(&g_deg_in[dst[e]], 1);
    }
}

// ---------------- scan + norms ------------------------------------------------
__global__ void scanA_kernel() {
    __shared__ int s[CHUNK];
    int t = threadIdx.x, b = blockIdx.x;
    int idx = b * CHUNK + t;
    int v = (idx < NNODES) ? g_deg_in[idx] : 0;
    s[t] = v;
    __syncthreads();
    for (int off = CHUNK / 2; off > 0; off >>= 1) {
        if (t < off) s[t] += s[t + off];
        __syncthreads();
    }
    if (t == 0) g_chunk_sum[b] = s[0];
}

__global__ void scanB_kernel() {
    __shared__ int s[128];
    int t = threadIdx.x;
    int v = (t < NCHUNK) ? g_chunk_sum[t] : 0;
    s[t] = v;
    __syncthreads();
    for (int off = 1; off < 128; off <<= 1) {
        int x = (t >= off) ? s[t - off] : 0;
        __syncthreads();
        s[t] += x;
        __syncthreads();
    }
    if (t < NCHUNK) g_chunk_off[t] = s[t] - v;
    if (t == 0) g_row_ptr[NNODES] = NEDGES;
}

__global__ void scanC_kernel() {
    __shared__ int s[CHUNK];
    int t = threadIdx.x, b = blockIdx.x;
    int idx = b * CHUNK + t;
    int v = (idx < NNODES) ? g_deg_in[idx] : 0;
    s[t] = v;
    __syncthreads();
    for (int off = 1; off < CHUNK; off <<= 1) {
        int x = (t >= off) ? s[t - off] : 0;
        __syncthreads();
        s[t] += x;
        __syncthreads();
    }
    if (idx < NNODES) {
        int excl = g_chunk_off[b] + s[t] - v;
        g_row_ptr[idx] = excl;
        g_cursor[idx]  = excl;
        int dins = v; if (dins < 1) dins = 1;
        int dofs = g_deg_out[idx]; if (dofs < 1) dofs = 1;
        g_norm_d[idx] = rsqrtf((float)dins);
        g_norm_s[idx] = rsqrtf((float)dofs);
    }
}

__global__ void csr_fill_kernel(const int* __restrict__ src, const int* __restrict__ dst) {
    int e = blockIdx.x * blockDim.x + threadIdx.x;
    if (e < NEDGES) {
        int d = dst[e];
        int pos = atomicAdd(&g_cursor[d], 1);
        g_csr_src[pos] = src[e];
    }
}

// ---------------- embedding pooling (warp per node, fp16 output) -------------
__global__ void embed_kernel(const int* __restrict__ feats, const float* __restrict__ emb) {
    int gt   = blockIdx.x * blockDim.x + threadIdx.x;
    int node = gt >> 5;
    int lane = gt & 31;
    if (node >= NNODES) return;

    int tok = feats[node * SEQLEN + lane];
    int cnt = __popc(__ballot_sync(0xffffffffu, tok != 0));
    if (cnt < 1) cnt = 1;

    float4 s  = make_float4(0.f, 0.f, 0.f, 0.f);
    float4 mx = make_float4(-INFINITY, -INFINITY, -INFINITY, -INFINITY);

#pragma unroll
    for (int t = 0; t < 32; t++) {
        int tk = __shfl_sync(0xffffffffu, tok, t);
        float4 v = make_float4(0.f, 0.f, 0.f, 0.f);
        if (tk != 0) v = *(const float4*)&emb[(size_t)tk * EMBD + lane * 4];
        s.x += v.x; s.y += v.y; s.z += v.z; s.w += v.w;
        mx.x = fmaxf(mx.x, v.x); mx.y = fmaxf(mx.y, v.y);
        mx.z = fmaxf(mx.z, v.z); mx.w = fmaxf(mx.w, v.w);
    }
    float inv = 1.0f / (float)cnt;
    __half2 h0 = __float22half2_rn(make_float2(s.x * inv, s.y * inv));
    __half2 h1 = __float22half2_rn(make_float2(s.z * inv, s.w * inv));
    __half2 m0 = __float22half2_rn(make_float2(mx.x, mx.y));
    __half2 m1 = __float22half2_rn(make_float2(mx.z, mx.w));
    size_t base = (size_t)node * INFEAT;
    *(uint2*)&g_hh[base + lane * 4]        = make_uint2(*(unsigned*)&h0, *(unsigned*)&h1);
    *(uint2*)&g_hh[base + EMBD + lane * 4] = make_uint2(*(unsigned*)&m0, *(unsigned*)&m1);
}

// ---------------- prep W1: [K][N] fp32 -> [N][K] fp16 ------------------------
__global__ void prep_w1_kernel(const float* __restrict__ W1) {
    int i = blockIdx.x * blockDim.x + threadIdx.x;   // 65536
    int n = i >> 8, k = i & 255;
    g_w1h[n * INFEAT + k] = __float2half(W1[k * NHID + n]);
}

// ---------------- GEMM1 via mma.sync fp16 m16n8k16 ---------------------------
#define KC 32
#define AW 20                   // words per smem row (32 halves + 8 pad)
#define STAGE_W (128 * AW)
#define G1_SMEM (4 * STAGE_W * 4)   // 40960 bytes

__global__ __launch_bounds__(256, 2)
void gemm1_mma_kernel() {
    extern __shared__ __align__(16) uint32_t smem[];
    uint32_t* As = smem;
    uint32_t* Bs = smem + 2 * STAGE_W;

    int tid = threadIdx.x, wid = tid >> 5, lane = tid & 31;
    int wm = wid & 3, wn = wid >> 2;
    int g = lane >> 2, tig = lane & 3;
    int bm = blockIdx.x * 128, bn = blockIdx.y * 128;

    int lrow = tid >> 1, lhw = (tid & 1) * 8;

    float acc[2][8][4];
#pragma unroll
    for (int mi = 0; mi < 2; mi++)
#pragma unroll
        for (int ni = 0; ni < 8; ni++)
#pragma unroll
            for (int q = 0; q < 4; q++) acc[mi][ni][q] = 0.f;

    uint4 ar[2], br[2];
    {
        int arow = bm + lrow;
        ar[0] = make_uint4(0, 0, 0, 0); ar[1] = ar[0];
        if (arow < NNODES) {
            const uint4* sa = (const uint4*)&g_hh[(size_t)arow * INFEAT + 2 * lhw];
            ar[0] = sa[0]; ar[1] = sa[1];
        }
        const uint4* sb = (const uint4*)&g_w1h[(bn + lrow) * INFEAT + 2 * lhw];
        br[0] = sb[0]; br[1] = sb[1];
    }
    *(uint4*)&As[lrow * AW + lhw]     = ar[0];
    *(uint4*)&As[lrow * AW + lhw + 4] = ar[1];
    *(uint4*)&Bs[lrow * AW + lhw]     = br[0];
    *(uint4*)&Bs[lrow * AW + lhw + 4] = br[1];
    __syncthreads();

    const int NKC = INFEAT / KC;   // 8
    for (int kc = 0; kc < NKC; kc++) {
        int cur = kc & 1, nxt = cur ^ 1;
        if (kc + 1 < NKC) {
            int k0 = (kc + 1) * KC;
            int arow = bm + lrow;
            ar[0] = make_uint4(0, 0, 0, 0); ar[1] = ar[0];
            if (arow < NNODES) {
                const uint4* sa = (const uint4*)&g_hh[(size_t)arow * INFEAT + k0 + 2 * lhw];
                ar[0] = sa[0]; ar[1] = sa[1];
            }
            const uint4* sb = (const uint4*)&g_w1h[(bn + lrow) * INFEAT + k0 + 2 * lhw];
            br[0] = sb[0]; br[1] = sb[1];
        }

        const uint32_t* Ac = &As[cur * STAGE_W];
        const uint32_t* Bc = &Bs[cur * STAGE_W];
#pragma unroll
        for (int ks = 0; ks < 2; ks++) {
            int kb = ks * 8 + tig;
            uint32_t af[2][4];
#pragma unroll
            for (int mi = 0; mi < 2; mi++) {
                int r = wm * 32 + mi * 16 + g;
                af[mi][0] = Ac[r * AW + kb];
                af[mi][1] = Ac[(r + 8) * AW + kb];
                af[mi][2] = Ac[r * AW + kb + 4];
                af[mi][3] = Ac[(r + 8) * AW + kb + 4];
            }
#pragma unroll
            for (int ni = 0; ni < 8; ni++) {
                int nr = wn * 64 + ni * 8 + g;
                uint32_t b0 = Bc[nr * AW + kb];
                uint32_t b1 = Bc[nr * AW + kb + 4];
                mma_f16(acc[0][ni], af[0], b0, b1);
                mma_f16(acc[1][ni], af[1], b0, b1);
            }
        }

        if (kc + 1 < NKC) {
            __syncthreads();
            *(uint4*)&As[nxt * STAGE_W + lrow * AW + lhw]     = ar[0];
            *(uint4*)&As[nxt * STAGE_W + lrow * AW + lhw + 4] = ar[1];
            *(uint4*)&Bs[nxt * STAGE_W + lrow * AW + lhw]     = br[0];
            *(uint4*)&Bs[nxt * STAGE_W + lrow * AW + lhw + 4] = br[1];
            __syncthreads();
        }
    }

#pragma unroll
    for (int mi = 0; mi < 2; mi++) {
        int r0 = bm + wm * 32 + mi * 16 + g;
        int r1 = r0 + 8;
#pragma unroll
        for (int ni = 0; ni < 8; ni++) {
            int col = bn + wn * 64 + ni * 8 + tig * 2;
            if (r0 < NNODES) {
                __half2 p = __float22half2_rn(make_float2(acc[mi][ni][0], acc[mi][ni][1]));
                *(unsigned*)&g_hw1h[(size_t)r0 * NHID + col] = *(unsigned*)&p;
            }
            if (r1 < NNODES) {
                __half2 p = __float22half2_rn(make_float2(acc[mi][ni][2], acc[mi][ni][3]));
                *(unsigned*)&g_hw1h[(size_t)r1 * NHID + col] = *(unsigned*)&p;
            }
        }
    }
}

// ---------------- agg layer 1 (fp16 messages, fp16 out) ----------------------
__global__ void agg1_kernel(const float* __restrict__ b1) {
    int gt   = blockIdx.x * blockDim.x + threadIdx.x;
    int node = gt >> 5;
    int lane = gt & 31;
    if (node >= NNODES) return;

    int beg = g_row_ptr[node], end = g_row_ptr[node + 1];
    float acc[8] = {0.f, 0.f, 0.f, 0.f, 0.f, 0.f, 0.f, 0.f};

    int e = beg;
    for (; e + 1 < end; e += 2) {
        int s0 = g_csr_src[e], s1 = g_csr_src[e + 1];
        float n0 = g_norm_s[s0], n1 = g_norm_s[s1];
        uint4 u0 = *(const uint4*)&g_hw1h[(size_t)s0 * NHID + lane * 8];
        uint4 u1 = *(const uint4*)&g_hw1h[(size_t)s1 * NHID + lane * 8];
        const unsigned* w0 = &u0.x;
        const unsigned* w1 = &u1.x;
#pragma unroll
        for (int j = 0; j < 4; j++) {
            float2 f0 = __half22float2(*(const __half2*)&w0[j]);
            float2 f1 = __half22float2(*(const __half2*)&w1[j]);
            acc[2 * j]     += f0.x * n0 + f1.x * n1;
            acc[2 * j + 1] += f0.y * n0 + f1.y * n1;
        }
    }
    if (e < end) {
        int s0 = g_csr_src[e];
        float n0 = g_norm_s[s0];
        uint4 u0 = *(const uint4*)&g_hw1h[(size_t)s0 * NHID + lane * 8];
        const unsigned* w0 = &u0.x;
#pragma unroll
        for (int j = 0; j < 4; j++) {
            float2 f0 = __half22float2(*(const __half2*)&w0[j]);
            acc[2 * j]     += f0.x * n0;
            acc[2 * j + 1] += f0.y * n0;
        }
    }

    float nd = g_norm_d[node];
    float4 bb0 = *(const float4*)&b1[lane * 8];
    float4 bb1 = *(const float4*)&b1[lane * 8 + 4];
    float o[8];
    o[0] = fmaxf(acc[0] * nd + bb0.x, 0.f);
    o[1] = fmaxf(acc[1] * nd + bb0.y, 0.f);
    o[2] = fmaxf(acc[2] * nd + bb0.z, 0.f);
    o[3] = fmaxf(acc[3] * nd + bb0.w, 0.f);
    o[4] = fmaxf(acc[4] * nd + bb1.x, 0.f);
    o[5] = fmaxf(acc[5] * nd + bb1.y, 0.f);
    o[6] = fmaxf(acc[6] * nd + bb1.z, 0.f);
    o[7] = fmaxf(acc[7] * nd + bb1.w, 0.f);
    __half2 p0 = __float22half2_rn(make_float2(o[0], o[1]));
    __half2 p1 = __float22half2_rn(make_float2(o[2], o[3]));
    __half2 p2 = __float22half2_rn(make_float2(o[4], o[5]));
    __half2 p3 = __float22half2_rn(make_float2(o[6], o[7]));
    *(uint4*)&g_out1h[(size_t)node * NHID + lane * 8] =
        make_uint4(*(unsigned*)&p0, *(unsigned*)&p1, *(unsigned*)&p2, *(unsigned*)&p3);
}

// ---------------- GEMM2: hws2h = fp16((out1 @ W2) * norm_s), f32x2 -----------
__global__ __launch_bounds__(256)
void gemm2_kernel(const float* __restrict__ W2) {
    __shared__ __align__(16) float Ws[NHID * NCLS];
    for (int i = threadIdx.x; i < (NHID * NCLS) / 4; i += blockDim.x)
        ((float4*)Ws)[i] = ((const float4*)W2)[i];
    __syncthreads();

    int row = blockIdx.x * blockDim.x + threadIdx.x;
    if (row >= NNODES) return;

    ull acc[NCLS / 2];
#pragma unroll
    for (int c = 0; c < NCLS / 2; c++) acc[c] = 0ull;

    const __half* a = &g_out1h[(size_t)row * NHID];
    for (int k0 = 0; k0 < NHID; k0 += 8) {
        uint4 u = *(const uint4*)&a[k0];
        const unsigned* uw = &u.x;
        float a8[8];
#pragma unroll
        for (int j = 0; j < 4; j++) {
            float2 f = __half22float2(*(const __half2*)&uw[j]);
            a8[2 * j] = f.x; a8[2 * j + 1] = f.y;
        }
#pragma unroll
        for (int kk = 0; kk < 8; kk++) {
            ull ad = dup2(a8[kk]);
            const ull* w = (const ull*)&Ws[(k0 + kk) * NCLS];
#pragma unroll
            for (int c = 0; c < NCLS / 2; c++) acc[c] = ffma2(ad, w[c], acc[c]);
        }
    }
    float ns = g_norm_s[row];
    unsigned po[NCLS / 2];
#pragma unroll
    for (int c = 0; c < NCLS / 2; c++) {
        float lo, hi;
        unpack2(acc[c], lo, hi);
        __half2 p = __float22half2_rn(make_float2(lo * ns, hi * ns));
        po[c] = *(unsigned*)&p;
    }
    uint4* dst = (uint4*)&g_hws2h[(size_t)row * NCLS];
#pragma unroll
    for (int c = 0; c < NCLS / 8; c++)
        dst[c] = make_uint4(po[4 * c], po[4 * c + 1], po[4 * c + 2], po[4 * c + 3]);
}

// ---------------- agg layer 2 (fp16 messages) --------------------------------
__global__ void agg2_kernel(const float* __restrict__ b2, float* __restrict__ out) {
    int gt   = blockIdx.x * blockDim.x + threadIdx.x;
    int node = gt >> 5;
    int lane = gt & 31;
    if (node >= NNODES) return;

    int beg = g_row_ptr[node], end = g_row_ptr[node + 1];
    float2 acc = make_float2(0.f, 0.f);
    bool act = lane < (NCLS / 2);
    for (int e = beg; e < end; e++) {
        int s = g_csr_src[e];
        unsigned w = act ? *(const unsigned*)&g_hws2h[(size_t)s * NCLS + lane * 2] : 0u;
        float2 f = __half22float2(*(const __half2*)&w);
        acc.x += f.x; acc.y += f.y;
    }
    if (act) {
        float nd = g_norm_d[node];
        float2 bb = *(const float2*)&b2[lane * 2];
        *(float2*)&out[(size_t)node * NCLS + lane * 2] =
            make_float2(acc.x * nd + bb.x, acc.y * nd + bb.y);
    }
}

// ---------------- launch ------------------------------------------------------
static cudaStream_t g_s2 = 0;
static cudaEvent_t  g_ev_fork = 0, g_ev_w1 = 0, g_ev_join = 0;

extern "C" void kernel_launch(void* const* d_in, const int* in_sizes, int n_in,
                              void* d_out, int out_size) {
    const int*   feats = (const int*)d_in[0];
    const int*   src   = (const int*)d_in[1];
    const int*   dst   = (const int*)d_in[2];
    const float* emb   = (const float*)d_in[3];
    const float* W1    = (const float*)d_in[4];
    const float* b1    = (const float*)d_in[5];
    const float* W2    = (const float*)d_in[6];
    const float* b2    = (const float*)d_in[7];
    float*       out   = (float*)d_out;

    if (!g_s2) {
        cudaStreamCreateWithFlags(&g_s2, cudaStreamNonBlocking);
        cudaEventCreateWithFlags(&g_ev_fork, cudaEventDisableTiming);
        cudaEventCreateWithFlags(&g_ev_w1, cudaEventDisableTiming);
        cudaEventCreateWithFlags(&g_ev_join, cudaEventDisableTiming);
        cudaFuncSetAttribute(gemm1_mma_kernel,
                             cudaFuncAttributeMaxDynamicSharedMemorySize, G1_SMEM);
    }

    // fork side stream
    cudaEventRecord(g_ev_fork, 0);
    cudaStreamWaitEvent(g_s2, g_ev_fork, 0);

    // Submission order: 3 tiny/parallel s2 kernels first so embed is the 4th
    // submitted launch (ncu profiles submission idx 3). Execution schedule is
    // unchanged: s2 kernels run concurrently with embed from t=0.
    prep_w1_kernel<<<256, 256, 0, g_s2>>>(W1);                             // sub 0 (s2)
    cudaEventRecord(g_ev_w1, g_s2);
    zero_degs_kernel<<<(NNODES + 511) / 512, 512, 0, g_s2>>>();            // sub 1 (s2)
    degree_kernel<<<(NEDGES + 511) / 512, 512, 0, g_s2>>>(src, dst);       // sub 2 (s2)
    embed_kernel<<<(NNODES * 32 + 255) / 256, 256>>>(feats, emb);          // sub 3 (main) <- profiled
    scanA_kernel<<<NCHUNK, CHUNK, 0, g_s2>>>();                            // sub 4 (s2)
    scanB_kernel<<<1, 128, 0, g_s2>>>();                                   // sub 5 (s2)
    scanC_kernel<<<NCHUNK, CHUNK, 0, g_s2>>>();                            // sub 6 (s2)
    csr_fill_kernel<<<(NEDGES + 511) / 512, 512, 0, g_s2>>>(src, dst);     // sub 7 (s2)
    cudaEventRecord(g_ev_join, g_s2);

    // main chain: gemm1 after embed (and W1 image)
    cudaStreamWaitEvent(0, g_ev_w1, 0);
    gemm1_mma_kernel<<<dim3(MTILES, 2), 256, G1_SMEM>>>();

    // agg1 needs CSR + norms (s2) and gemm1 (main)
    cudaStreamWaitEvent(0, g_ev_join, 0);
    agg1_kernel<<<(NNODES * 32 + 255) / 256, 256>>>(b1);
    gemm2_kernel<<<(NNODES + 255) / 256, 256>>>(W2);
    agg2_kernel<<<(NNODES * 32 + 255) / 256, 256>>>(b2, out);
}

// round 16
// speedup vs baseline: 1.0254x; 1.0215x over previous
#include <cuda_runtime.h>
#include <cuda_fp16.h>
#include <math.h>
#include <stdint.h>

#define NNODES 50000
#define NEDGES 800000
#define NTOK   100000
#define SEQLEN 32
#define EMBD   128
#define INFEAT 256
#define NHID   256
#define NCLS   40

#define CHUNK   512
#define NCHUNK  98      // 98*512 = 50176 >= 50000
#define MTILES  391     // ceil(50000/128)

typedef unsigned long long ull;

// ---------------- scratch (device globals; no allocation allowed) ------------
__device__ int   g_deg_out[NNODES];
__device__ int   g_deg_in[NNODES];
__device__ float g_norm_s[NNODES];
__device__ float g_norm_d[NNODES];
__device__ int   g_row_ptr[NNODES + 1];
__device__ int   g_cursor[NNODES];
__device__ int   g_chunk_sum[NCHUNK];
__device__ int   g_chunk_off[NCHUNK];
__device__ int   g_csr_src[NEDGES];
__device__ __align__(16) float g_zero_row[EMBD];                  // static zero-init
__device__ __align__(16) __half g_hh[(size_t)NNODES * INFEAT];    // pooled emb fp16
__device__ __align__(16) __half g_w1h[NHID * INFEAT];             // W1^T [n][k] fp16
__device__ __align__(16) __half g_hw1h[(size_t)NNODES * NHID];    // h@W1 fp16
__device__ __align__(16) __half g_out1h[(size_t)NNODES * NHID];   // relu(...) fp16
__device__ __align__(16) __half g_hws2h[(size_t)NNODES * NCLS];   // (out1@W2)*norm_s fp16

// ---------------- helpers -----------------------------------------------------
__device__ __forceinline__ ull ffma2(ull a, ull b, ull c) {
    ull d;
    asm("fma.rn.f32x2 %0, %1, %2, %3;" : "=l"(d) : "l"(a), "l"(b), "l"(c));
    return d;
}
__device__ __forceinline__ ull dup2(float x) {
    ull d;
    asm("mov.b64 %0, {%1, %1};" : "=l"(d) : "f"(x));
    return d;
}
__device__ __forceinline__ void unpack2(ull v, float& lo, float& hi) {
    asm("mov.b64 {%0, %1}, %2;" : "=f"(lo), "=f"(hi) : "l"(v));
}
__device__ __forceinline__ void mma_f16(float* c, const uint32_t* a, uint32_t b0, uint32_t b1) {
    asm volatile(
        "mma.sync.aligned.m16n8k16.row.col.f32.f16.f16.f32 "
        "{%0,%1,%2,%3}, {%4,%5,%6,%7}, {%8,%9}, {%0,%1,%2,%3};"
        : "+f"(c[0]), "+f"(c[1]), "+f"(c[2]), "+f"(c[3])
        : "r"(a[0]), "r"(a[1]), "r"(a[2]), "r"(a[3]), "r"(b0), "r"(b1));
}
__device__ __forceinline__ uint32_t smem_u32(const void* p) {
    uint32_t a;
    asm("{ .reg .u64 t; cvta.to.shared.u64 t, %1; cvt.u32.u64 %0, t; }" : "=r"(a) : "l"(p));
    return a;
}
__device__ __forceinline__ void ldsm_x4(uint32_t* r, uint32_t addr) {
    asm volatile("ldmatrix.sync.aligned.m8n8.x4.shared.b16 {%0,%1,%2,%3}, [%4];"
                 : "=r"(r[0]), "=r"(r[1]), "=r"(r[2]), "=r"(r[3]) : "r"(addr));
}

// ---------------- degree ------------------------------------------------------
__global__ void zero_degs_kernel() {
    int i = blockIdx.x * blockDim.x + threadIdx.x;
    if (i < NNODES) { g_deg_out[i] = 0; g_deg_in[i] = 0; }
}

__global__ void degree_kernel(const int* __restrict__ src, const int* __restrict__ dst) {
    int e = blockIdx.x * blockDim.x + threadIdx.x;
    if (e < NEDGES) {
        atomicAdd(&g_deg_out[src[e]], 1);
        atomicAdd(&g_deg_in[dst[e]], 1);
    }
}

// ---------------- scan + norms ------------------------------------------------
__global__ void scanA_kernel() {
    __shared__ int s[CHUNK];
    int t = threadIdx.x, b = blockIdx.x;
    int idx = b * CHUNK + t;
    int v = (idx < NNODES) ? g_deg_in[idx] : 0;
    s[t] = v;
    __syncthreads();
    for (int off = CHUNK / 2; off > 0; off >>= 1) {
        if (t < off) s[t] += s[t + off];
        __syncthreads();
    }
    if (t == 0) g_chunk_sum[b] = s[0];
}

__global__ void scanB_kernel() {
    __shared__ int s[128];
    int t = threadIdx.x;
    int v = (t < NCHUNK) ? g_chunk_sum[t] : 0;
    s[t] = v;
    __syncthreads();
    for (int off = 1; off < 128; off <<= 1) {
        int x = (t >= off) ? s[t - off] : 0;
        __syncthreads();
        s[t] += x;
        __syncthreads();
    }
    if (t < NCHUNK) g_chunk_off[t] = s[t] - v;
    if (t == 0) g_row_ptr[NNODES] = NEDGES;
}

__global__ void scanC_kernel() {
    __shared__ int s[CHUNK];
    int t = threadIdx.x, b = blockIdx.x;
    int idx = b * CHUNK + t;
    int v = (idx < NNODES) ? g_deg_in[idx] : 0;
    s[t] = v;
    __syncthreads();
    for (int off = 1; off < CHUNK; off <<= 1) {
        int x = (t >= off) ? s[t - off] : 0;
        __syncthreads();
        s[t] += x;
        __syncthreads();
    }
    if (idx < NNODES) {
        int excl = g_chunk_off[b] + s[t] - v;
        g_row_ptr[idx] = excl;
        g_cursor[idx]  = excl;
        int dins = v; if (dins < 1) dins = 1;
        int dofs = g_deg_out[idx]; if (dofs < 1) dofs = 1;
        g_norm_d[idx] = rsqrtf((float)dins);
        g_norm_s[idx] = rsqrtf((float)dofs);
    }
}

__global__ void csr_fill_kernel(const int* __restrict__ src, const int* __restrict__ dst) {
    int e = blockIdx.x * blockDim.x + threadIdx.x;
    if (e < NEDGES) {
        int d = dst[e];
        int pos = atomicAdd(&g_cursor[d], 1);
        g_csr_src[pos] = src[e];
    }
}

// ---------------- embedding pooling (warp per node, fp16 output) -------------
__global__ void embed_kernel(const int* __restrict__ feats, const float* __restrict__ emb) {
    int gt   = blockIdx.x * blockDim.x + threadIdx.x;
    int node = gt >> 5;
    int lane = gt & 31;
    if (node >= NNODES) return;

    int tok = feats[node * SEQLEN + lane];
    int cnt = __popc(__ballot_sync(0xffffffffu, tok != 0));
    if (cnt < 1) cnt = 1;

    float4 s  = make_float4(0.f, 0.f, 0.f, 0.f);
    float4 mx = make_float4(-INFINITY, -INFINITY, -INFINITY, -INFINITY);

#pragma unroll
    for (int t = 0; t < 32; t++) {
        int tk = __shfl_sync(0xffffffffu, tok, t);
        const float* p = (tk != 0) ? &emb[(size_t)tk * EMBD] : g_zero_row;
        float4 v = *(const float4*)&p[lane * 4];
        s.x += v.x; s.y += v.y; s.z += v.z; s.w += v.w;
        mx.x = fmaxf(mx.x, v.x); mx.y = fmaxf(mx.y, v.y);
        mx.z = fmaxf(mx.z, v.z); mx.w = fmaxf(mx.w, v.w);
    }
    float inv = 1.0f / (float)cnt;
    __half2 h0 = __float22half2_rn(make_float2(s.x * inv, s.y * inv));
    __half2 h1 = __float22half2_rn(make_float2(s.z * inv, s.w * inv));
    __half2 m0 = __float22half2_rn(make_float2(mx.x, mx.y));
    __half2 m1 = __float22half2_rn(make_float2(mx.z, mx.w));
    size_t base = (size_t)node * INFEAT;
    *(uint2*)&g_hh[base + lane * 4]        = make_uint2(*(unsigned*)&h0, *(unsigned*)&h1);
    *(uint2*)&g_hh[base + EMBD + lane * 4] = make_uint2(*(unsigned*)&m0, *(unsigned*)&m1);
}

// ---------------- prep W1: [K][N] fp32 -> [N][K] fp16 ------------------------
__global__ void prep_w1_kernel(const float* __restrict__ W1) {
    int i = blockIdx.x * blockDim.x + threadIdx.x;   // 65536
    int n = i >> 8, k = i & 255;
    g_w1h[n * INFEAT + k] = __float2half(W1[k * NHID + n]);
}

// ---------------- GEMM1 via mma.sync fp16 m16n8k16 + ldmatrix ----------------
#define KC 32
#define AW 20                   // words per smem row (32 halves + 8 pad)
#define STAGE_W (128 * AW)
#define G1_SMEM (4 * STAGE_W * 4)   // 40960 bytes

__global__ __launch_bounds__(256, 2)
void gemm1_mma_kernel() {
    extern __shared__ __align__(16) uint32_t smem[];
    uint32_t* As = smem;
    uint32_t* Bs = smem + 2 * STAGE_W;

    int tid = threadIdx.x, wid = tid >> 5, lane = tid & 31;
    int wm = wid & 3, wn = wid >> 2;
    int g = lane >> 2, tig = lane & 3;
    int bm = blockIdx.x * 128, bn = blockIdx.y * 128;

    int lrow = tid >> 1, lhw = (tid & 1) * 8;

    uint32_t sbA = smem_u32(smem);
    uint32_t sbB = sbA + 2 * STAGE_W * 4;

    // per-lane ldmatrix offsets (bytes)
    int phase = lane >> 3, j = lane & 7;
    // A x4: lanes 0-7 rows+0 @k0, 8-15 rows+8 @k0, 16-23 rows+0 @k8, 24-31 rows+8 @k8
    uint32_t aoff = (((phase & 1) * 8 + j) * AW + (phase >> 1) * 4) * 4;
    // B x4 (pair p): lanes 0-7 rows+0 @k0, 8-15 rows+0 @k8, 16-23 rows+8 @k0, 24-31 rows+8 @k8
    uint32_t boff = (((phase >> 1) * 8 + j) * AW + (phase & 1) * 4) * 4;

    float acc[2][8][4];
#pragma unroll
    for (int mi = 0; mi < 2; mi++)
#pragma unroll
        for (int ni = 0; ni < 8; ni++)
#pragma unroll
            for (int q = 0; q < 4; q++) acc[mi][ni][q] = 0.f;

    uint4 ar[2], br[2];
    {
        int arow = bm + lrow;
        ar[0] = make_uint4(0, 0, 0, 0); ar[1] = ar[0];
        if (arow < NNODES) {
            const uint4* sa = (const uint4*)&g_hh[(size_t)arow * INFEAT + 2 * lhw];
            ar[0] = sa[0]; ar[1] = sa[1];
        }
        const uint4* sb = (const uint4*)&g_w1h[(bn + lrow) * INFEAT + 2 * lhw];
        br[0] = sb[0]; br[1] = sb[1];
    }
    *(uint4*)&As[lrow * AW + lhw]     = ar[0];
    *(uint4*)&As[lrow * AW + lhw + 4] = ar[1];
    *(uint4*)&Bs[lrow * AW + lhw]     = br[0];
    *(uint4*)&Bs[lrow * AW + lhw + 4] = br[1];
    __syncthreads();

    const int NKC = INFEAT / KC;   // 8
    for (int kc = 0; kc < NKC; kc++) {
        int cur = kc & 1, nxt = cur ^ 1;
        if (kc + 1 < NKC) {
            int k0 = (kc + 1) * KC;
            int arow = bm + lrow;
            ar[0] = make_uint4(0, 0, 0, 0); ar[1] = ar[0];
            if (arow < NNODES) {
                const uint4* sa = (const uint4*)&g_hh[(size_t)arow * INFEAT + k0 + 2 * lhw];
                ar[0] = sa[0]; ar[1] = sa[1];
            }
            const uint4* sb = (const uint4*)&g_w1h[(bn + lrow) * INFEAT + k0 + 2 * lhw];
            br[0] = sb[0]; br[1] = sb[1];
        }

        uint32_t Acb = sbA + cur * STAGE_W * 4;
        uint32_t Bcb = sbB + cur * STAGE_W * 4;
#pragma unroll
        for (int ks = 0; ks < 2; ks++) {
            uint32_t kbyte = ks * 8 * 4;   // k16 step = 8 words
            uint32_t af[2][4];
#pragma unroll
            for (int mi = 0; mi < 2; mi++) {
                uint32_t addr = Acb + (uint32_t)((wm * 32 + mi * 16) * AW * 4) + kbyte + aoff;
                ldsm_x4(af[mi], addr);
            }
            uint32_t bf[4][4];
#pragma unroll
            for (int p = 0; p < 4; p++) {
                uint32_t addr = Bcb + (uint32_t)((wn * 64 + p * 16) * AW * 4) + kbyte + boff;
                ldsm_x4(bf[p], addr);
            }
#pragma unroll
            for (int p = 0; p < 4; p++) {
                mma_f16(acc[0][2 * p],     af[0], bf[p][0], bf[p][1]);
                mma_f16(acc[1][2 * p],     af[1], bf[p][0], bf[p][1]);
                mma_f16(acc[0][2 * p + 1], af[0], bf[p][2], bf[p][3]);
                mma_f16(acc[1][2 * p + 1], af[1], bf[p][2], bf[p][3]);
            }
        }

        if (kc + 1 < NKC) {
            __syncthreads();
            *(uint4*)&As[nxt * STAGE_W + lrow * AW + lhw]     = ar[0];
            *(uint4*)&As[nxt * STAGE_W + lrow * AW + lhw + 4] = ar[1];
            *(uint4*)&Bs[nxt * STAGE_W + lrow * AW + lhw]     = br[0];
            *(uint4*)&Bs[nxt * STAGE_W + lrow * AW + lhw + 4] = br[1];
            __syncthreads();
        }
    }

#pragma unroll
    for (int mi = 0; mi < 2; mi++) {
        int r0 = bm + wm * 32 + mi * 16 + g;
        int r1 = r0 + 8;
#pragma unroll
        for (int ni = 0; ni < 8; ni++) {
            int col = bn + wn * 64 + ni * 8 + tig * 2;
            if (r0 < NNODES) {
                __half2 p = __float22half2_rn(make_float2(acc[mi][ni][0], acc[mi][ni][1]));
                *(unsigned*)&g_hw1h[(size_t)r0 * NHID + col] = *(unsigned*)&p;
            }
            if (r1 < NNODES) {
                __half2 p = __float22half2_rn(make_float2(acc[mi][ni][2], acc[mi][ni][3]));
                *(unsigned*)&g_hw1h[(size_t)r1 * NHID + col] = *(unsigned*)&p;
            }
        }
    }
}

// ---------------- agg layer 1 (fp16 messages, fp16 out) ----------------------
__global__ void agg1_kernel(const float* __restrict__ b1) {
    int gt   = blockIdx.x * blockDim.x + threadIdx.x;
    int node = gt >> 5;
    int lane = gt & 31;
    if (node >= NNODES) return;

    int beg = g_row_ptr[node], end = g_row_ptr[node + 1];
    float acc[8] = {0.f, 0.f, 0.f, 0.f, 0.f, 0.f, 0.f, 0.f};

    int e = beg;
    for (; e + 1 < end; e += 2) {
        int s0 = g_csr_src[e], s1 = g_csr_src[e + 1];
        float n0 = g_norm_s[s0], n1 = g_norm_s[s1];
        uint4 u0 = *(const uint4*)&g_hw1h[(size_t)s0 * NHID + lane * 8];
        uint4 u1 = *(const uint4*)&g_hw1h[(size_t)s1 * NHID + lane * 8];
        const unsigned* w0 = &u0.x;
        const unsigned* w1 = &u1.x;
#pragma unroll
        for (int j = 0; j < 4; j++) {
            float2 f0 = __half22float2(*(const __half2*)&w0[j]);
            float2 f1 = __half22float2(*(const __half2*)&w1[j]);
            acc[2 * j]     += f0.x * n0 + f1.x * n1;
            acc[2 * j + 1] += f0.y * n0 + f1.y * n1;
        }
    }
    if (e < end) {
        int s0 = g_csr_src[e];
        float n0 = g_norm_s[s0];
        uint4 u0 = *(const uint4*)&g_hw1h[(size_t)s0 * NHID + lane * 8];
        const unsigned* w0 = &u0.x;
#pragma unroll
        for (int j = 0; j < 4; j++) {
            float2 f0 = __half22float2(*(const __half2*)&w0[j]);
            acc[2 * j]     += f0.x * n0;
            acc[2 * j + 1] += f0.y * n0;
        }
    }

    float nd = g_norm_d[node];
    float4 bb0 = *(const float4*)&b1[lane * 8];
    float4 bb1 = *(const float4*)&b1[lane * 8 + 4];
    float o[8];
    o[0] = fmaxf(acc[0] * nd + bb0.x, 0.f);
    o[1] = fmaxf(acc[1] * nd + bb0.y, 0.f);
    o[2] = fmaxf(acc[2] * nd + bb0.z, 0.f);
    o[3] = fmaxf(acc[3] * nd + bb0.w, 0.f);
    o[4] = fmaxf(acc[4] * nd + bb1.x, 0.f);
    o[5] = fmaxf(acc[5] * nd + bb1.y, 0.f);
    o[6] = fmaxf(acc[6] * nd + bb1.z, 0.f);
    o[7] = fmaxf(acc[7] * nd + bb1.w, 0.f);
    __half2 p0 = __float22half2_rn(make_float2(o[0], o[1]));
    __half2 p1 = __float22half2_rn(make_float2(o[2], o[3]));
    __half2 p2 = __float22half2_rn(make_float2(o[4], o[5]));
    __half2 p3 = __float22half2_rn(make_float2(o[6], o[7]));
    *(uint4*)&g_out1h[(size_t)node * NHID + lane * 8] =
        make_uint4(*(unsigned*)&p0, *(unsigned*)&p1, *(unsigned*)&p2, *(unsigned*)&p3);
}

// ---------------- GEMM2: hws2h = fp16((out1 @ W2) * norm_s), f32x2 -----------
__global__ __launch_bounds__(256)
void gemm2_kernel(const float* __restrict__ W2) {
    __shared__ __align__(16) float Ws[NHID * NCLS];
    for (int i = threadIdx.x; i < (NHID * NCLS) / 4; i += blockDim.x)
        ((float4*)Ws)[i] = ((const float4*)W2)[i];
    __syncthreads();

    int row = blockIdx.x * blockDim.x + threadIdx.x;
    if (row >= NNODES) return;

    ull acc[NCLS / 2];
#pragma unroll
    for (int c = 0; c < NCLS / 2; c++) acc[c] = 0ull;

    const __half* a = &g_out1h[(size_t)row * NHID];
    for (int k0 = 0; k0 < NHID; k0 += 8) {
        uint4 u = *(const uint4*)&a[k0];
        const unsigned* uw = &u.x;
        float a8[8];
#pragma unroll
        for (int j = 0; j < 4; j++) {
            float2 f = __half22float2(*(const __half2*)&uw[j]);
            a8[2 * j] = f.x; a8[2 * j + 1] = f.y;
        }
#pragma unroll
        for (int kk = 0; kk < 8; kk++) {
            ull ad = dup2(a8[kk]);
            const ull* w = (const ull*)&Ws[(k0 + kk) * NCLS];
#pragma unroll
            for (int c = 0; c < NCLS / 2; c++) acc[c] = ffma2(ad, w[c], acc[c]);
        }
    }
    float ns = g_norm_s[row];
    unsigned po[NCLS / 2];
#pragma unroll
    for (int c = 0; c < NCLS / 2; c++) {
        float lo, hi;
        unpack2(acc[c], lo, hi);
        __half2 p = __float22half2_rn(make_float2(lo * ns, hi * ns));
        po[c] = *(unsigned*)&p;
    }
    uint4* dst = (uint4*)&g_hws2h[(size_t)row * NCLS];
#pragma unroll
    for (int c = 0; c < NCLS / 8; c++)
        dst[c] = make_uint4(po[4 * c], po[4 * c + 1], po[4 * c + 2], po[4 * c + 3]);
}

// ---------------- agg layer 2 (fp16 messages) --------------------------------
__global__ void agg2_kernel(const float* __restrict__ b2, float* __restrict__ out) {
    int gt   = blockIdx.x * blockDim.x + threadIdx.x;
    int node = gt >> 5;
    int lane = gt & 31;
    if (node >= NNODES) return;

    int beg = g_row_ptr[node], end = g_row_ptr[node + 1];
    float2 acc = make_float2(0.f, 0.f);
    bool act = lane < (NCLS / 2);
    for (int e = beg; e < end; e++) {
        int s = g_csr_src[e];
        unsigned w = act ? *(const unsigned*)&g_hws2h[(size_t)s * NCLS + lane * 2] : 0u;
        float2 f = __half22float2(*(const __half2*)&w);
        acc.x += f.x; acc.y += f.y;
    }
    if (act) {
        float nd = g_norm_d[node];
        float2 bb = *(const float2*)&b2[lane * 2];
        *(float2*)&out[(size_t)node * NCLS + lane * 2] =
            make_float2(acc.x * nd + bb.x, acc.y * nd + bb.y);
    }
}

// ---------------- launch ------------------------------------------------------
static cudaStream_t g_s2 = 0;
static cudaEvent_t  g_ev_fork = 0, g_ev_w1 = 0, g_ev_join = 0;

extern "C" void kernel_launch(void* const* d_in, const int* in_sizes, int n_in,
                              void* d_out, int out_size) {
    const int*   feats = (const int*)d_in[0];
    const int*   src   = (const int*)d_in[1];
    const int*   dst   = (const int*)d_in[2];
    const float* emb   = (const float*)d_in[3];
    const float* W1    = (const float*)d_in[4];
    const float* b1    = (const float*)d_in[5];
    const float* W2    = (const float*)d_in[6];
    const float* b2    = (const float*)d_in[7];
    float*       out   = (float*)d_out;

    if (!g_s2) {
        cudaStreamCreateWithFlags(&g_s2, cudaStreamNonBlocking);
        cudaEventCreateWithFlags(&g_ev_fork, cudaEventDisableTiming);
        cudaEventCreateWithFlags(&g_ev_w1, cudaEventDisableTiming);
        cudaEventCreateWithFlags(&g_ev_join, cudaEventDisableTiming);
        cudaFuncSetAttribute(gemm1_mma_kernel,
                             cudaFuncAttributeMaxDynamicSharedMemorySize, G1_SMEM);
    }

    // fork side stream
    cudaEventRecord(g_ev_fork, 0);
    cudaStreamWaitEvent(g_s2, g_ev_fork, 0);

    // round-13 submission order: gemm1 at launch idx 3 (ncu profile slot)
    embed_kernel<<<(NNODES * 32 + 255) / 256, 256>>>(feats, emb);          // 0 main
    prep_w1_kernel<<<256, 256, 0, g_s2>>>(W1);                             // 1 s2
    cudaEventRecord(g_ev_w1, g_s2);
    zero_degs_kernel<<<(NNODES + 511) / 512, 512, 0, g_s2>>>();            // 2 s2
    cudaStreamWaitEvent(0, g_ev_w1, 0);
    gemm1_mma_kernel<<<dim3(MTILES, 2), 256, G1_SMEM>>>();                 // 3 main
    degree_kernel<<<(NEDGES + 511) / 512, 512, 0, g_s2>>>(src, dst);       // 4 s2
    scanA_kernel<<<NCHUNK, CHUNK, 0, g_s2>>>();                            // 5 s2
    scanB_kernel<<<1, 128, 0, g_s2>>>();                                   // 6 s2
    scanC_kernel<<<NCHUNK, CHUNK, 0, g_s2>>>();                            // 7 s2
    csr_fill_kernel<<<(NEDGES + 511) / 512, 512, 0, g_s2>>>(src, dst);     // 8 s2
    cudaEventRecord(g_ev_join, g_s2);

    // agg1 needs CSR + norms (s2) and gemm1 (main)
    cudaStreamWaitEvent(0, g_ev_join, 0);
    agg1_kernel<<<(NNODES * 32 + 255) / 256, 256>>>(b1);
    gemm2_kernel<<<(NNODES + 255) / 256, 256>>>(W2);
    agg2_kernel<<<(NNODES * 32 + 255) / 256, 256>>>(b2, out);
}

// round 17
// speedup vs baseline: 1.0447x; 1.0189x over previous
#include <cuda_runtime.h>
#include <cuda_fp16.h>
#include <math.h>
#include <stdint.h>

#define NNODES 50000
#define NEDGES 800000
#define NTOK   100000
#define SEQLEN 32
#define EMBD   128
#define INFEAT 256
#define NHID   256
#define NCLS   40

#define CHUNK   512
#define NCHUNK  98      // 98*512 = 50176 >= 50000
#define MTILES  391     // ceil(50000/128)

typedef unsigned long long ull;

// ---------------- scratch (device globals; no allocation allowed) ------------
__device__ int   g_deg_out[NNODES];
__device__ int   g_deg_in[NNODES];
__device__ float g_norm_s[NNODES];
__device__ float g_norm_d[NNODES];
__device__ int   g_row_ptr[NNODES + 1];
__device__ int   g_cursor[NNODES];
__device__ int   g_chunk_sum[NCHUNK];
__device__ int   g_chunk_off[NCHUNK];
__device__ int   g_csr_src[NEDGES];
__device__ __align__(16) float g_zero_row[EMBD];                  // static zero-init
__device__ __align__(16) __half g_hh[(size_t)NNODES * INFEAT];    // pooled emb fp16
__device__ __align__(16) __half g_w1h[NHID * INFEAT];             // W1^T [n][k] fp16
__device__ __align__(16) __half g_hw1h[(size_t)NNODES * NHID];    // h@W1 fp16
__device__ __align__(16) __half g_out1h[(size_t)NNODES * NHID];   // relu(...) fp16
__device__ __align__(16) __half g_hws2h[(size_t)NNODES * NCLS];   // (out1@W2)*norm_s fp16

// ---------------- helpers -----------------------------------------------------
__device__ __forceinline__ ull ffma2(ull a, ull b, ull c) {
    ull d;
    asm("fma.rn.f32x2 %0, %1, %2, %3;" : "=l"(d) : "l"(a), "l"(b), "l"(c));
    return d;
}
__device__ __forceinline__ ull dup2(float x) {
    ull d;
    asm("mov.b64 %0, {%1, %1};" : "=l"(d) : "f"(x));
    return d;
}
__device__ __forceinline__ void unpack2(ull v, float& lo, float& hi) {
    asm("mov.b64 {%0, %1}, %2;" : "=f"(lo), "=f"(hi) : "l"(v));
}
__device__ __forceinline__ void mma_f16(float* c, const uint32_t* a, uint32_t b0, uint32_t b1) {
    asm volatile(
        "mma.sync.aligned.m16n8k16.row.col.f32.f16.f16.f32 "
        "{%0,%1,%2,%3}, {%4,%5,%6,%7}, {%8,%9}, {%0,%1,%2,%3};"
        : "+f"(c[0]), "+f"(c[1]), "+f"(c[2]), "+f"(c[3])
        : "r"(a[0]), "r"(a[1]), "r"(a[2]), "r"(a[3]), "r"(b0), "r"(b1));
}
__device__ __forceinline__ uint32_t smem_u32(const void* p) {
    uint32_t a;
    asm("{ .reg .u64 t; cvta.to.shared.u64 t, %1; cvt.u32.u64 %0, t; }" : "=r"(a) : "l"(p));
    return a;
}
__device__ __forceinline__ void ldsm_x4(uint32_t* r, uint32_t addr) {
    asm volatile("ldmatrix.sync.aligned.m8n8.x4.shared.b16 {%0,%1,%2,%3}, [%4];"
                 : "=r"(r[0]), "=r"(r[1]), "=r"(r[2]), "=r"(r[3]) : "r"(addr));
}
__device__ __forceinline__ void cpa16(uint32_t dst, const void* src) {
    asm volatile("cp.async.cg.shared.global [%0], [%1], 16;" :: "r"(dst), "l"(src));
}
#define CPA_COMMIT() asm volatile("cp.async.commit_group;" ::: "memory")

// ---------------- degree ------------------------------------------------------
__global__ void degree_kernel(const int* __restrict__ src, const int* __restrict__ dst) {
    int e = blockIdx.x * blockDim.x + threadIdx.x;
    if (e < NEDGES) {
        atomicAdd(&g_deg_out[src[e]], 1);
        atomicAdd(&g_deg_in[dst[e]], 1);
    }
}

// ---------------- scan + norms ------------------------------------------------
__global__ void scanA_kernel() {
    __shared__ int s[CHUNK];
    int t = threadIdx.x, b = blockIdx.x;
    int idx = b * CHUNK + t;
    int v = (idx < NNODES) ? g_deg_in[idx] : 0;
    s[t] = v;
    __syncthreads();
    for (int off = CHUNK / 2; off > 0; off >>= 1) {
        if (t < off) s[t] += s[t + off];
        __syncthreads();
    }
    if (t == 0) g_chunk_sum[b] = s[0];
}

__global__ void scanB_kernel() {
    __shared__ int s[128];
    int t = threadIdx.x;
    int v = (t < NCHUNK) ? g_chunk_sum[t] : 0;
    s[t] = v;
    __syncthreads();
    for (int off = 1; off < 128; off <<= 1) {
        int x = (t >= off) ? s[t - off] : 0;
        __syncthreads();
        s[t] += x;
        __syncthreads();
    }
    if (t < NCHUNK) g_chunk_off[t] = s[t] - v;
    if (t == 0) g_row_ptr[NNODES] = NEDGES;
}

__global__ void scanC_kernel() {
    __shared__ int s[CHUNK];
    int t = threadIdx.x, b = blockIdx.x;
    int idx = b * CHUNK + t;
    int v = (idx < NNODES) ? g_deg_in[idx] : 0;
    s[t] = v;
    __syncthreads();
    for (int off = 1; off < CHUNK; off <<= 1) {
        int x = (t >= off) ? s[t - off] : 0;
        __syncthreads();
        s[t] += x;
        __syncthreads();
    }
    if (idx < NNODES) {
        int excl = g_chunk_off[b] + s[t] - v;
        g_row_ptr[idx] = excl;
        g_cursor[idx]  = excl;
        int dins = v; if (dins < 1) dins = 1;
        int dofs = g_deg_out[idx]; if (dofs < 1) dofs = 1;
        g_norm_d[idx] = rsqrtf((float)dins);
        g_norm_s[idx] = rsqrtf((float)dofs);
    }
}

__global__ void csr_fill_kernel(const int* __restrict__ src, const int* __restrict__ dst) {
    int e = blockIdx.x * blockDim.x + threadIdx.x;
    if (e < NEDGES) {
        int d = dst[e];
        int pos = atomicAdd(&g_cursor[d], 1);
        g_csr_src[pos] = src[e];
    }
}

// ---------------- embedding pooling (warp per node, fp16 output) -------------
__global__ void embed_kernel(const int* __restrict__ feats, const float* __restrict__ emb) {
    int gt   = blockIdx.x * blockDim.x + threadIdx.x;
    int node = gt >> 5;
    int lane = gt & 31;
    if (node >= NNODES) return;

    int tok = feats[node * SEQLEN + lane];
    int cnt = __popc(__ballot_sync(0xffffffffu, tok != 0));
    if (cnt < 1) cnt = 1;

    float4 s  = make_float4(0.f, 0.f, 0.f, 0.f);
    float4 mx = make_float4(-INFINITY, -INFINITY, -INFINITY, -INFINITY);

#pragma unroll
    for (int t = 0; t < 32; t++) {
        int tk = __shfl_sync(0xffffffffu, tok, t);
        const float* p = (tk != 0) ? &emb[(size_t)tk * EMBD] : g_zero_row;
        float4 v = *(const float4*)&p[lane * 4];
        s.x += v.x; s.y += v.y; s.z += v.z; s.w += v.w;
        mx.x = fmaxf(mx.x, v.x); mx.y = fmaxf(mx.y, v.y);
        mx.z = fmaxf(mx.z, v.z); mx.w = fmaxf(mx.w, v.w);
    }
    float inv = 1.0f / (float)cnt;
    __half2 h0 = __float22half2_rn(make_float2(s.x * inv, s.y * inv));
    __half2 h1 = __float22half2_rn(make_float2(s.z * inv, s.w * inv));
    __half2 m0 = __float22half2_rn(make_float2(mx.x, mx.y));
    __half2 m1 = __float22half2_rn(make_float2(mx.z, mx.w));
    size_t base = (size_t)node * INFEAT;
    *(uint2*)&g_hh[base + lane * 4]        = make_uint2(*(unsigned*)&h0, *(unsigned*)&h1);
    *(uint2*)&g_hh[base + EMBD + lane * 4] = make_uint2(*(unsigned*)&m0, *(unsigned*)&m1);
}

// ---------------- prep W1 (+ zero degs, merged) -------------------------------
__global__ void prep_w1_kernel(const float* __restrict__ W1) {
    int i = blockIdx.x * blockDim.x + threadIdx.x;   // 65536
    int n = i >> 8, k = i & 255;
    g_w1h[n * INFEAT + k] = __float2half(W1[k * NHID + n]);
    if (i < NNODES) { g_deg_out[i] = 0; g_deg_in[i] = 0; }
}

// ---------------- GEMM1: fp16 mma + ldmatrix + 3-stage cp.async --------------
#define KC 32
#define AW 20                   // words per smem row (32 halves + 8 pad)
#define STAGE_W (128 * AW)      // per operand per stage (words)
#define G1_SMEM (6 * STAGE_W * 4)   // 3 stages x (A+B) = 61440 bytes
#define NKC (INFEAT / KC)       // 8

__device__ __forceinline__ void g1_issue(uint32_t sbA, uint32_t sbB, int buf, int stage,
                                         int bm, int bn, int lrow, int lhb) {
    // lhb: byte offset 0 or 32 within the 64B k-chunk row
    int arow = bm + lrow; if (arow >= NNODES) arow = NNODES - 1;   // clamp (stores guarded)
    uint32_t dstA = sbA + (uint32_t)(buf * STAGE_W + lrow * AW) * 4 + lhb;
    const __half* srcA = &g_hh[(size_t)arow * INFEAT + stage * KC] + lhb / 2;
    cpa16(dstA, srcA);
    cpa16(dstA + 16, srcA + 8);
    uint32_t dstB = sbB + (uint32_t)(buf * STAGE_W + lrow * AW) * 4 + lhb;
    const __half* srcB = &g_w1h[(bn + lrow) * INFEAT + stage * KC] + lhb / 2;
    cpa16(dstB, srcB);
    cpa16(dstB + 16, srcB + 8);
}

__global__ __launch_bounds__(256, 2)
void gemm1_mma_kernel() {
    extern __shared__ __align__(16) uint32_t smem[];

    int tid = threadIdx.x, wid = tid >> 5, lane = tid & 31;
    int wm = wid & 3, wn = wid >> 2;
    int g = lane >> 2, tig = lane & 3;
    int bm = blockIdx.x * 128, bn = blockIdx.y * 128;

    int lrow = tid >> 1, lhb = (tid & 1) * 32;   // byte offset within row

    uint32_t sbA = smem_u32(smem);
    uint32_t sbB = sbA + 3 * STAGE_W * 4;

    // per-lane ldmatrix offsets (bytes)
    int phase = lane >> 3, j = lane & 7;
    uint32_t aoff = (uint32_t)((((phase & 1) * 8 + j) * AW + (phase >> 1) * 4) * 4);
    uint32_t boff = (uint32_t)((((phase >> 1) * 8 + j) * AW + (phase & 1) * 4) * 4);

    float acc[2][8][4];
#pragma unroll
    for (int mi = 0; mi < 2; mi++)
#pragma unroll
        for (int ni = 0; ni < 8; ni++)
#pragma unroll
            for (int q = 0; q < 4; q++) acc[mi][ni][q] = 0.f;

    // prologue: stages 0 and 1
    g1_issue(sbA, sbB, 0, 0, bm, bn, lrow, lhb); CPA_COMMIT();
    g1_issue(sbA, sbB, 1, 1, bm, bn, lrow, lhb); CPA_COMMIT();

#pragma unroll
    for (int i = 0; i < NKC; i++) {
        if (i < NKC - 1)
            asm volatile("cp.async.wait_group 1;" ::: "memory");
        else
            asm volatile("cp.async.wait_group 0;" ::: "memory");
        __syncthreads();

        int buf = i % 3;
        uint32_t Acb = sbA + (uint32_t)(buf * STAGE_W * 4);
        uint32_t Bcb = sbB + (uint32_t)(buf * STAGE_W * 4);
#pragma unroll
        for (int ks = 0; ks < 2; ks++) {
            uint32_t kbyte = ks * 32;
            uint32_t af[2][4];
#pragma unroll
            for (int mi = 0; mi < 2; mi++)
                ldsm_x4(af[mi], Acb + (uint32_t)((wm * 32 + mi * 16) * AW * 4) + kbyte + aoff);
            uint32_t bf[4][4];
#pragma unroll
            for (int p = 0; p < 4; p++)
                ldsm_x4(bf[p], Bcb + (uint32_t)((wn * 64 + p * 16) * AW * 4) + kbyte + boff);
#pragma unroll
            for (int p = 0; p < 4; p++) {
                mma_f16(acc[0][2 * p],     af[0], bf[p][0], bf[p][1]);
                mma_f16(acc[1][2 * p],     af[1], bf[p][0], bf[p][1]);
                mma_f16(acc[0][2 * p + 1], af[0], bf[p][2], bf[p][3]);
                mma_f16(acc[1][2 * p + 1], af[1], bf[p][2], bf[p][3]);
            }
        }

        if (i + 2 < NKC) {
            g1_issue(sbA, sbB, (i + 2) % 3, i + 2, bm, bn, lrow, lhb);
            CPA_COMMIT();
        }
    }

    // epilogue: fp16 store
#pragma unroll
    for (int mi = 0; mi < 2; mi++) {
        int r0 = bm + wm * 32 + mi * 16 + g;
        int r1 = r0 + 8;
#pragma unroll
        for (int ni = 0; ni < 8; ni++) {
            int col = bn + wn * 64 + ni * 8 + tig * 2;
            if (r0 < NNODES) {
                __half2 p = __float22half2_rn(make_float2(acc[mi][ni][0], acc[mi][ni][1]));
                *(unsigned*)&g_hw1h[(size_t)r0 * NHID + col] = *(unsigned*)&p;
            }
            if (r1 < NNODES) {
                __half2 p = __float22half2_rn(make_float2(acc[mi][ni][2], acc[mi][ni][3]));
                *(unsigned*)&g_hw1h[(size_t)r1 * NHID + col] = *(unsigned*)&p;
            }
        }
    }
}

// ---------------- agg layer 1 (fp16 messages, fp16 out) ----------------------
__global__ void agg1_kernel(const float* __restrict__ b1) {
    int gt   = blockIdx.x * blockDim.x + threadIdx.x;
    int node = gt >> 5;
    int lane = gt & 31;
    if (node >= NNODES) return;

    int beg = g_row_ptr[node], end = g_row_ptr[node + 1];
    float acc[8] = {0.f, 0.f, 0.f, 0.f, 0.f, 0.f, 0.f, 0.f};

    int e = beg;
    for (; e + 1 < end; e += 2) {
        int s0 = g_csr_src[e], s1 = g_csr_src[e + 1];
        float n0 = g_norm_s[s0], n1 = g_norm_s[s1];
        uint4 u0 = *(const uint4*)&g_hw1h[(size_t)s0 * NHID + lane * 8];
        uint4 u1 = *(const uint4*)&g_hw1h[(size_t)s1 * NHID + lane * 8];
        const unsigned* w0 = &u0.x;
        const unsigned* w1 = &u1.x;
#pragma unroll
        for (int j = 0; j < 4; j++) {
            float2 f0 = __half22float2(*(const __half2*)&w0[j]);
            float2 f1 = __half22float2(*(const __half2*)&w1[j]);
            acc[2 * j]     += f0.x * n0 + f1.x * n1;
            acc[2 * j + 1] += f0.y * n0 + f1.y * n1;
        }
    }
    if (e < end) {
        int s0 = g_csr_src[e];
        float n0 = g_norm_s[s0];
        uint4 u0 = *(const uint4*)&g_hw1h[(size_t)s0 * NHID + lane * 8];
        const unsigned* w0 = &u0.x;
#pragma unroll
        for (int j = 0; j < 4; j++) {
            float2 f0 = __half22float2(*(const __half2*)&w0[j]);
            acc[2 * j]     += f0.x * n0;
            acc[2 * j + 1] += f0.y * n0;
        }
    }

    float nd = g_norm_d[node];
    float4 bb0 = *(const float4*)&b1[lane * 8];
    float4 bb1 = *(const float4*)&b1[lane * 8 + 4];
    float o[8];
    o[0] = fmaxf(acc[0] * nd + bb0.x, 0.f);
    o[1] = fmaxf(acc[1] * nd + bb0.y, 0.f);
    o[2] = fmaxf(acc[2] * nd + bb0.z, 0.f);
    o[3] = fmaxf(acc[3] * nd + bb0.w, 0.f);
    o[4] = fmaxf(acc[4] * nd + bb1.x, 0.f);
    o[5] = fmaxf(acc[5] * nd + bb1.y, 0.f);
    o[6] = fmaxf(acc[6] * nd + bb1.z, 0.f);
    o[7] = fmaxf(acc[7] * nd + bb1.w, 0.f);
    __half2 p0 = __float22half2_rn(make_float2(o[0], o[1]));
    __half2 p1 = __float22half2_rn(make_float2(o[2], o[3]));
    __half2 p2 = __float22half2_rn(make_float2(o[4], o[5]));
    __half2 p3 = __float22half2_rn(make_float2(o[6], o[7]));
    *(uint4*)&g_out1h[(size_t)node * NHID + lane * 8] =
        make_uint4(*(unsigned*)&p0, *(unsigned*)&p1, *(unsigned*)&p2, *(unsigned*)&p3);
}

// ---------------- GEMM2: hws2h = fp16((out1 @ W2) * norm_s), f32x2 -----------
__global__ __launch_bounds__(256)
void gemm2_kernel(const float* __restrict__ W2) {
    __shared__ __align__(16) float Ws[NHID * NCLS];
    for (int i = threadIdx.x; i < (NHID * NCLS) / 4; i += blockDim.x)
        ((float4*)Ws)[i] = ((const float4*)W2)[i];
    __syncthreads();

    int row = blockIdx.x * blockDim.x + threadIdx.x;
    if (row >= NNODES) return;

    ull acc[NCLS / 2];
#pragma unroll
    for (int c = 0; c < NCLS / 2; c++) acc[c] = 0ull;

    const __half* a = &g_out1h[(size_t)row * NHID];
    for (int k0 = 0; k0 < NHID; k0 += 8) {
        uint4 u = *(const uint4*)&a[k0];
        const unsigned* uw = &u.x;
        float a8[8];
#pragma unroll
        for (int j = 0; j < 4; j++) {
            float2 f = __half22float2(*(const __half2*)&uw[j]);
            a8[2 * j] = f.x; a8[2 * j + 1] = f.y;
        }
#pragma unroll
        for (int kk = 0; kk < 8; kk++) {
            ull ad = dup2(a8[kk]);
            const ull* w = (const ull*)&Ws[(k0 + kk) * NCLS];
#pragma unroll
            for (int c = 0; c < NCLS / 2; c++) acc[c] = ffma2(ad, w[c], acc[c]);
        }
    }
    float ns = g_norm_s[row];
    unsigned po[NCLS / 2];
#pragma unroll
    for (int c = 0; c < NCLS / 2; c++) {
        float lo, hi;
        unpack2(acc[c], lo, hi);
        __half2 p = __float22half2_rn(make_float2(lo * ns, hi * ns));
        po[c] = *(unsigned*)&p;
    }
    uint4* dst = (uint4*)&g_hws2h[(size_t)row * NCLS];
#pragma unroll
    for (int c = 0; c < NCLS / 8; c++)
        dst[c] = make_uint4(po[4 * c], po[4 * c + 1], po[4 * c + 2], po[4 * c + 3]);
}

// ---------------- agg layer 2 (fp16 messages) --------------------------------
__global__ void agg2_kernel(const float* __restrict__ b2, float* __restrict__ out) {
    int gt   = blockIdx.x * blockDim.x + threadIdx.x;
    int node = gt >> 5;
    int lane = gt & 31;
    if (node >= NNODES) return;

    int beg = g_row_ptr[node], end = g_row_ptr[node + 1];
    float2 acc = make_float2(0.f, 0.f);
    bool act = lane < (NCLS / 2);
    for (int e = beg; e < end; e++) {
        int s = g_csr_src[e];
        unsigned w = act ? *(const unsigned*)&g_hws2h[(size_t)s * NCLS + lane * 2] : 0u;
        float2 f = __half22float2(*(const __half2*)&w);
        acc.x += f.x; acc.y += f.y;
    }
    if (act) {
        float nd = g_norm_d[node];
        float2 bb = *(const float2*)&b2[lane * 2];
        *(float2*)&out[(size_t)node * NCLS + lane * 2] =
            make_float2(acc.x * nd + bb.x, acc.y * nd + bb.y);
    }
}

// ---------------- launch ------------------------------------------------------
static cudaStream_t g_s2 = 0;
static cudaEvent_t  g_ev_fork = 0, g_ev_w1 = 0, g_ev_join = 0;

extern "C" void kernel_launch(void* const* d_in, const int* in_sizes, int n_in,
                              void* d_out, int out_size) {
    const int*   feats = (const int*)d_in[0];
    const int*   src   = (const int*)d_in[1];
    const int*   dst   = (const int*)d_in[2];
    const float* emb   = (const float*)d_in[3];
    const float* W1    = (const float*)d_in[4];
    const float* b1    = (const float*)d_in[5];
    const float* W2    = (const float*)d_in[6];
    const float* b2    = (const float*)d_in[7];
    float*       out   = (float*)d_out;

    if (!g_s2) {
        cudaStreamCreateWithFlags(&g_s2, cudaStreamNonBlocking);
        cudaEventCreateWithFlags(&g_ev_fork, cudaEventDisableTiming);
        cudaEventCreateWithFlags(&g_ev_w1, cudaEventDisableTiming);
        cudaEventCreateWithFlags(&g_ev_join, cudaEventDisableTiming);
        cudaFuncSetAttribute(gemm1_mma_kernel,
                             cudaFuncAttributeMaxDynamicSharedMemorySize, G1_SMEM);
    }

    // fork side stream
    cudaEventRecord(g_ev_fork, 0);
    cudaStreamWaitEvent(g_s2, g_ev_fork, 0);

    // submission order keeps gemm1 at launch idx 3 (ncu profile slot)
    embed_kernel<<<(NNODES * 32 + 255) / 256, 256>>>(feats, emb);          // 0 main
    prep_w1_kernel<<<256, 256, 0, g_s2>>>(W1);                             // 1 s2 (also zeros degs)
    cudaEventRecord(g_ev_w1, g_s2);
    degree_kernel<<<(NEDGES + 511) / 512, 512, 0, g_s2>>>(src, dst);       // 2 s2
    cudaStreamWaitEvent(0, g_ev_w1, 0);
    gemm1_mma_kernel<<<dim3(MTILES, 2), 256, G1_SMEM>>>();                 // 3 main
    scanA_kernel<<<NCHUNK, CHUNK, 0, g_s2>>>();                            // 4 s2
    scanB_kernel<<<1, 128, 0, g_s2>>>();                                   // 5 s2
    scanC_kernel<<<NCHUNK, CHUNK, 0, g_s2>>>();                            // 6 s2
    csr_fill_kernel<<<(NEDGES + 511) / 512, 512, 0, g_s2>>>(src, dst);     // 7 s2
    cudaEventRecord(g_ev_join, g_s2);

    // agg1 needs CSR + norms (s2) and gemm1 (main)
    cudaStreamWaitEvent(0, g_ev_join, 0);
    agg1_kernel<<<(NNODES * 32 + 255) / 256, 256>>>(b1);
    gemm2_kernel<<<(NNODES + 255) / 256, 256>>>(W2);
    agg2_kernel<<<(NNODES * 32 + 255) / 256, 256>>>(b2, out);
}